// round 14
// baseline (speedup 1.0000x reference)
#include <cuda_runtime.h>
#include <math.h>
#include <stdint.h>

#define PATCH 7
#define PP 49

// Scratch: fragment-ordered hi/lo activation buffers (ping/pong), plain final
// activations, and fragment-ordered hi/lo weights.
__device__ float g_fhA[1 << 18];
__device__ float g_flA[1 << 18];
__device__ float g_fhB[1 << 18];
__device__ float g_flB[1 << 18];
__device__ float g_act[1 << 18];
__device__ float g_wf[1 << 19];

__device__ __forceinline__ uint32_t f32_to_tf32(float x) {
    uint32_t r;
    asm("cvt.rna.tf32.f32 %0, %1;" : "=r"(r) : "f"(x));
    return r;
}

__device__ __forceinline__ void mma_tf32(float* c, const uint32_t* a, uint32_t b0, uint32_t b1) {
    asm volatile(
        "mma.sync.aligned.m16n8k8.row.col.f32.tf32.tf32.f32 "
        "{%0,%1,%2,%3}, {%4,%5,%6,%7}, {%8,%9}, {%0,%1,%2,%3};\n"
        : "+f"(c[0]), "+f"(c[1]), "+f"(c[2]), "+f"(c[3])
        : "r"(a[0]), "r"(a[1]), "r"(a[2]), "r"(a[3]), "r"(b0), "r"(b1));
}

__device__ __forceinline__ void cp_async16(void* smem_dst, const void* gmem_src) {
    uint32_t s = (uint32_t)__cvta_generic_to_shared(smem_dst);
    asm volatile("cp.async.ca.shared.global [%0], [%1], 16;\n" :: "r"(s), "l"(gmem_src));
}
__device__ __forceinline__ void cp_async_commit() {
    asm volatile("cp.async.commit_group;\n");
}
__device__ __forceinline__ void cp_async_wait1() {
    asm volatile("cp.async.wait_group 1;\n");
}
__device__ __forceinline__ void cp_async_wait0() {
    asm volatile("cp.async.wait_group 0;\n");
}

// ---------------------------------------------------------------------------
// prep: blocks [0,256): weights -> nf-paired fragment hi/lo:
//   Wf f4 index (per layer): ((nb*32 + k8)*2 + nfp)*64 + hl*32 + lane
// blocks [256,512): queries -> fragment hi/lo activations:
//   act f4 index: (mb*8 + t8)*256 + su, su = k8l*64 + mi*32 + lane, where
//   f4 = {x(r,c), x(r+8,c), x(r,c+4), x(r+8,c+4)},
//   r = mb*32 + mi*16 + g, c = t8*32 + k8l*8 + tg, lane = g*4 + tg.
// ---------------------------------------------------------------------------
__global__ void __launch_bounds__(256)
prep_kernel(const float* __restrict__ W0, const float* __restrict__ W1,
            const float* __restrict__ W2, const float* __restrict__ W3,
            const float* __restrict__ Qin,
            float* __restrict__ Wf, float* __restrict__ aHi, float* __restrict__ aLo,
            int N) {
    if (blockIdx.x < 256) {
        const int t = blockIdx.x * blockDim.x + threadIdx.x;   // 0..65535
        const int lane = t & 31;
        const int nfp = (t >> 5) & 1;
        const int k8 = (t >> 6) & 31;
        const int nb = (t >> 11) & 7;
        const int layer = t >> 14;
        const float* W = (layer == 0) ? W0 : (layer == 1) ? W1 : (layer == 2) ? W2 : W3;
        const int g = lane >> 2;
        const int tg = lane & 3;

        float h[4], l[4];
#pragma unroll
        for (int nfl = 0; nfl < 2; nfl++) {
            const int n = nb * 32 + (nfp * 2 + nfl) * 8 + g;
            const float w0 = W[(size_t)(k8 * 8 + tg) * N + n];
            const float w1 = W[(size_t)(k8 * 8 + tg + 4) * N + n];
            h[nfl * 2 + 0] = __uint_as_float(f32_to_tf32(w0));
            h[nfl * 2 + 1] = __uint_as_float(f32_to_tf32(w1));
            l[nfl * 2 + 0] = __uint_as_float(f32_to_tf32(w0 - h[nfl * 2 + 0]));
            l[nfl * 2 + 1] = __uint_as_float(f32_to_tf32(w1 - h[nfl * 2 + 1]));
        }
        float4* out = reinterpret_cast<float4*>(Wf);
        const int base = (t >> 5) * 64;
        out[base + lane]      = make_float4(h[0], h[1], h[2], h[3]);
        out[base + 32 + lane] = make_float4(l[0], l[1], l[2], l[3]);
    } else {
        const int id = (blockIdx.x - 256) * blockDim.x + threadIdx.x;  // 0..65535
        const int su = id & 255;
        const int t8 = (id >> 8) & 7;
        const int mb = id >> 11;
        const int k8l = su >> 6;
        const int mi = (su >> 5) & 1;
        const int lane = su & 31;
        const int g = lane >> 2;
        const int tg = lane & 3;
        const int r = mb * 32 + mi * 16 + g;
        const int c = t8 * 32 + k8l * 8 + tg;
        const float x0 = Qin[(size_t)r * N + c];
        const float x1 = Qin[(size_t)(r + 8) * N + c];
        const float x2 = Qin[(size_t)r * N + c + 4];
        const float x3 = Qin[(size_t)(r + 8) * N + c + 4];
        const float h0 = __uint_as_float(f32_to_tf32(x0));
        const float h1 = __uint_as_float(f32_to_tf32(x1));
        const float h2 = __uint_as_float(f32_to_tf32(x2));
        const float h3 = __uint_as_float(f32_to_tf32(x3));
        reinterpret_cast<float4*>(aHi)[id] = make_float4(h0, h1, h2, h3);
        reinterpret_cast<float4*>(aLo)[id] =
            make_float4(__uint_as_float(f32_to_tf32(x0 - h0)),
                        __uint_as_float(f32_to_tf32(x1 - h1)),
                        __uint_as_float(f32_to_tf32(x2 - h2)),
                        __uint_as_float(f32_to_tf32(x3 - h3)));
    }
}

// ---------------------------------------------------------------------------
// 3xTF32 GEMM, fragment-in / fragment-out, m32n64 block tile, 3-stage pipe.
// Block 256 thr (8 warps: wks = wid>>2 k-half, wn = wid&3 n16 tile).
// 8 iters of BK=32; per warp-iter: 12 LDS.128 -> 24 MMA.
// Stage (1536 f4 = 24 KB): Ah[256], Al[256], B[1024 = 2 strips x 512].
// Epilogue: 2-way split-K smem reduction + bias (+ReLU), then fragment-order
// hi/lo output over 2 slabs (FRAGOUT) or plain row-major C.
// Grid (4, 32) = 128 blocks, single wave.
// ---------------------------------------------------------------------------
template <bool RELU, bool FRAGOUT>
__global__ void __launch_bounds__(256)
gemm_tf32_kernel(const float* __restrict__ aHi, const float* __restrict__ aLo,
                 const float* __restrict__ WfL, const float* __restrict__ bias,
                 float* __restrict__ oHi, float* __restrict__ oLo,
                 float* __restrict__ Cplain, int M, int N, int K) {
    extern __shared__ float4 pool[];        // 3 stages x 1536 f4 = 72 KB

    const int tid = threadIdx.x;
    const int lane = tid & 31;
    const int wid = tid >> 5;
    const int wks = wid >> 2;               // k-half (0/1)
    const int wn = wid & 3;                 // n16 tile (0..3)
    const int g = lane >> 2;
    const int tg = lane & 3;

    const int mb = blockIdx.y;
    const int bx = blockIdx.x;
    const int iters = K >> 5;               // 8

    const float4* aHi4 = reinterpret_cast<const float4*>(aHi);
    const float4* aLo4 = reinterpret_cast<const float4*>(aLo);
    const float4* wf_nb = reinterpret_cast<const float4*>(WfL) + (size_t)bx * 8192;

    auto stage = [&](int t, int s) {
        float4* dst = pool + s * 1536;
        const size_t ao = (size_t)(mb * 8 + t) * 256 + tid;
        cp_async16(&dst[tid], &aHi4[ao]);
        cp_async16(&dst[256 + tid], &aLo4[ao]);
#pragma unroll
        for (int j = 0; j < 4; j++) {
            const int u = tid + j * 256;           // 0..1023
            const int nbl = u >> 9;
            const int w = u & 511;
            cp_async16(&dst[512 + u], wf_nb + (size_t)nbl * 4096 + (size_t)t * 512 + w);
        }
        cp_async_commit();
    };

    stage(0, 0);
    stage(1, 1);

    float acc[2][2][4];
#pragma unroll
    for (int mi = 0; mi < 2; mi++)
#pragma unroll
        for (int nfl = 0; nfl < 2; nfl++)
#pragma unroll
            for (int i = 0; i < 4; i++) acc[mi][nfl][i] = 0.f;

    const int nbl = wn >> 1;
    const int nfp = wn & 1;

    int s = 0;
    for (int t = 0; t < iters; t++) {
        if (t + 2 < iters) cp_async_wait1();
        else               cp_async_wait0();
        __syncthreads();
        if (t + 2 < iters) stage(t + 2, (s + 2) % 3);

        const float4* base = pool + s * 1536;
#pragma unroll
        for (int s2 = 0; s2 < 2; s2++) {
            const int k8l = wks * 2 + s2;
            const float4 bh = base[512 + nbl * 512 + (k8l * 2 + nfp) * 64 + lane];
            const float4 bl = base[512 + nbl * 512 + (k8l * 2 + nfp) * 64 + 32 + lane];
            const uint32_t bh0 = __float_as_uint(bh.x), bh1 = __float_as_uint(bh.y);
            const uint32_t bh2 = __float_as_uint(bh.z), bh3 = __float_as_uint(bh.w);
            const uint32_t bl0 = __float_as_uint(bl.x), bl1 = __float_as_uint(bl.y);
            const uint32_t bl2 = __float_as_uint(bl.z), bl3 = __float_as_uint(bl.w);
#pragma unroll
            for (int mi = 0; mi < 2; mi++) {
                const float4 ahv = base[k8l * 64 + mi * 32 + lane];
                const float4 alv = base[256 + k8l * 64 + mi * 32 + lane];
                uint32_t ahi[4] = {__float_as_uint(ahv.x), __float_as_uint(ahv.y),
                                   __float_as_uint(ahv.z), __float_as_uint(ahv.w)};
                uint32_t alo[4] = {__float_as_uint(alv.x), __float_as_uint(alv.y),
                                   __float_as_uint(alv.z), __float_as_uint(alv.w)};
                mma_tf32(acc[mi][0], ahi, bh0, bh1);
                mma_tf32(acc[mi][1], ahi, bh2, bh3);
                mma_tf32(acc[mi][0], ahi, bl0, bl1);
                mma_tf32(acc[mi][1], ahi, bl2, bl3);
                mma_tf32(acc[mi][0], alo, bh0, bh1);
                mma_tf32(acc[mi][1], alo, bh2, bh3);
            }
        }

        s = (s + 1) % 3;
    }

    // ---- 2-way split-K reduction via smem (pool[0..1023]) ----
    __syncthreads();
    float4* red = pool;
#pragma unroll
    for (int mi = 0; mi < 2; mi++)
#pragma unroll
        for (int nfl = 0; nfl < 2; nfl++)
            red[wid * 128 + (mi * 2 + nfl) * 32 + lane] =
                make_float4(acc[mi][nfl][0], acc[mi][nfl][1], acc[mi][nfl][2], acc[mi][nfl][3]);
    __syncthreads();

    float* stHi = reinterpret_cast<float*>(pool + 1024);   // 512 f4
    float* stLo = reinterpret_cast<float*>(pool + 1536);   // 512 f4

#pragma unroll
    for (int i = 0; i < 2; i++) {
        const int c = wid * 2 + i;          // 0..15
        const int wn_r = c >> 2;
        const int nfl = (c >> 1) & 1;
        const int mi = c & 1;
        const int set = mi * 2 + nfl;
        const float4 s0 = red[wn_r * 128 + set * 32 + lane];
        const float4 s1 = red[(wn_r + 4) * 128 + set * 32 + lane];
        float v[4];
        v[0] = s0.x + s1.x;
        v[1] = s0.y + s1.y;
        v[2] = s0.z + s1.z;
        v[3] = s0.w + s1.w;

        const int col = bx * 64 + wn_r * 16 + nfl * 8 + 2 * tg;
        const float b0v = bias[col];
        const float b1v = bias[col + 1];
        v[0] += b0v; v[1] += b1v; v[2] += b0v; v[3] += b1v;
        if (RELU) {
#pragma unroll
            for (int e = 0; e < 4; e++) v[e] = fmaxf(v[e], 0.f);
        }

        if (FRAGOUT) {
            const int idx = 2 * wn_r + nfl;     // 0..7
            const int slab = idx >> 2;
            const int k8l_n = idx & 3;
#pragma unroll
            for (int e = 0; e < 4; e++) {
                const int cc = 2 * tg + (e & 1);
                const int lane_c = g * 4 + (cc & 3);
                const int comp = (e >> 1) + 2 * (cc >> 2);
                const int su = slab * 256 + k8l_n * 64 + mi * 32 + lane_c;
                const float hi = __uint_as_float(f32_to_tf32(v[e]));
                stHi[su * 4 + comp] = hi;
                stLo[su * 4 + comp] = __uint_as_float(f32_to_tf32(v[e] - hi));
            }
        } else {
            const int row0 = mb * 32 + mi * 16 + g;
            *reinterpret_cast<float2*>(&Cplain[(size_t)row0 * N + col]) = make_float2(v[0], v[1]);
            *reinterpret_cast<float2*>(&Cplain[(size_t)(row0 + 8) * N + col]) = make_float2(v[2], v[3]);
        }
    }

    if (FRAGOUT) {
        __syncthreads();
#pragma unroll
        for (int j = 0; j < 2; j++) {
            const size_t dst = (size_t)(mb * 8 + 2 * bx + j) * 256 + tid;
            reinterpret_cast<float4*>(oHi)[dst] = pool[1024 + j * 256 + tid];
            reinterpret_cast<float4*>(oLo)[dst] = pool[1536 + j * 256 + tid];
        }
    }
}

// ---------------------------------------------------------------------------
// Patch gather + dot + indices. One block (256 threads) per query.
// Output layout in d_out (float32):
//   [0, N*49)        logits (n, py, px)
//   [N*49, N*49*5)   indices as float (n, py, px, {b,y,x,q})
// ---------------------------------------------------------------------------
__global__ void __launch_bounds__(256)
patch_kernel(const float* __restrict__ fm, const float* __restrict__ qe,
             const float* __restrict__ qpos, const int* __restrict__ shapes,
             float* __restrict__ out, int N, int Q, int D) {
    __shared__ float sq[256];
    const int n = blockIdx.x;
    if (n >= N) return;

    const int b = n / Q;
    const int q = n - b * Q;
    const int Hb = shapes[2 * b + 0];
    const int Wb = shapes[2 * b + 1];

    const float posx = qpos[2 * n + 0];
    const float posy = qpos[2 * n + 1];
    const int cy = (int)(posy * (float)Hb);
    const int cx = (int)(posx * (float)Wb);

    for (int d = threadIdx.x; d < D; d += blockDim.x)
        sq[d] = qe[(size_t)n * D + d];
    __syncthreads();

    const int warp = threadIdx.x >> 5;
    const int lane = threadIdx.x & 31;
    const float4* sq4 = reinterpret_cast<const float4*>(sq);
    const float4 q0 = sq4[lane];
    const float4 q1 = sq4[lane + 32];

    float* out_logits = out;
    float* out_idx = out + (size_t)N * PP;

    for (int p = warp; p < PP; p += 8) {
        const int dy = p / PATCH - PATCH / 2;
        const int dx = p % PATCH - PATCH / 2;
        int y = cy + dy;
        int x = cx + dx;
        y = min(max(y, 0), Hb - 1);
        x = min(max(x, 0), Wb - 1);

        const size_t row_off = (((size_t)b * Hb + y) * Wb + x) * (size_t)D;
        const float4* row = reinterpret_cast<const float4*>(fm + row_off);

        const float4 f0 = row[lane];
        const float4 f1 = row[lane + 32];

        float s = f0.x * q0.x + f0.y * q0.y + f0.z * q0.z + f0.w * q0.w;
        s = fmaf(f1.x, q1.x, s);
        s = fmaf(f1.y, q1.y, s);
        s = fmaf(f1.z, q1.z, s);
        s = fmaf(f1.w, q1.w, s);

#pragma unroll
        for (int off = 16; off; off >>= 1)
            s += __shfl_xor_sync(0xFFFFFFFFu, s, off);

        if (lane == 0) {
            out_logits[(size_t)n * PP + p] = s;
            float4 iv = make_float4((float)b, (float)y, (float)x, (float)q);
            *reinterpret_cast<float4*>(&out_idx[((size_t)n * PP + p) * 4]) = iv;
        }
    }
}

extern "C" void kernel_launch(void* const* d_in, const int* in_sizes, int n_in,
                              void* d_out, int out_size) {
    const float* fm      = (const float*)d_in[0];
    const float* queries = (const float*)d_in[1];
    const float* qpos    = (const float*)d_in[2];
    const int*   shapes  = (const int*)d_in[4];
    const float* W0 = (const float*)d_in[5];
    const float* b0 = (const float*)d_in[6];
    const float* W1 = (const float*)d_in[7];
    const float* b1 = (const float*)d_in[8];
    const float* W2 = (const float*)d_in[9];
    const float* b2 = (const float*)d_in[10];
    const float* W3 = (const float*)d_in[11];
    const float* b3 = (const float*)d_in[12];

    const int B = in_sizes[3];               // query_batch_offsets length
    const int D = in_sizes[6];               // bias length (256)
    const int N = in_sizes[1] / D;           // total queries (1024)
    const int Q = N / B;
    const int LSZ = 8 * 4096 * 4;            // floats per layer in Wf

    float *fhA, *flA, *fhB, *flB, *act, *wf;
    cudaGetSymbolAddress((void**)&fhA, g_fhA);
    cudaGetSymbolAddress((void**)&flA, g_flA);
    cudaGetSymbolAddress((void**)&fhB, g_fhB);
    cudaGetSymbolAddress((void**)&flB, g_flB);
    cudaGetSymbolAddress((void**)&act, g_act);
    cudaGetSymbolAddress((void**)&wf, g_wf);

    const int SMEM = 4608 * 16;              // 72 KB dynamic shared
    cudaFuncSetAttribute(gemm_tf32_kernel<true, true>,
                         cudaFuncAttributeMaxDynamicSharedMemorySize, SMEM);
    cudaFuncSetAttribute(gemm_tf32_kernel<false, false>,
                         cudaFuncAttributeMaxDynamicSharedMemorySize, SMEM);

    prep_kernel<<<512, 256>>>(W0, W1, W2, W3, queries, wf, fhA, flA, D);

    dim3 gblock(256);
    dim3 ggrid(D / 64, N / 32);              // (4, 32) = 128 blocks

    gemm_tf32_kernel<true,  true ><<<ggrid, gblock, SMEM>>>(fhA, flA, wf + 0 * LSZ, b0, fhB, flB, nullptr, N, D, D);
    gemm_tf32_kernel<true,  true ><<<ggrid, gblock, SMEM>>>(fhB, flB, wf + 1 * LSZ, b1, fhA, flA, nullptr, N, D, D);
    gemm_tf32_kernel<true,  true ><<<ggrid, gblock, SMEM>>>(fhA, flA, wf + 2 * LSZ, b2, fhB, flB, nullptr, N, D, D);
    gemm_tf32_kernel<false, false><<<ggrid, gblock, SMEM>>>(fhB, flB, wf + 3 * LSZ, b3, nullptr, nullptr, act, N, D, D);

    patch_kernel<<<N, 256>>>(fm, act, qpos, shapes, (float*)d_out, N, Q, D);
}